// round 13
// baseline (speedup 1.0000x reference)
#include <cuda_runtime.h>
#include <cuda_bf16.h>
#include <math.h>
#include <stdint.h>

// Problem constants
#define Bb  2
#define Tt  2048
#define Ee  2048
#define Hh  32
#define KVh 8
#define Dd  64
#define Mrows (Bb*Tt)          // 4096
#define QN  (Hh*Dd)            // 2048
#define KN  (KVh*Dd)           // 512

// Scratch (device globals — no allocations allowed)
__device__ float g_Q[(size_t)Mrows*QN];
__device__ float g_K[(size_t)Mrows*KN];
__device__ float g_V[(size_t)Mrows*KN];
__device__ float g_O[(size_t)Mrows*QN];

// ===========================================================================
// 3xTF32 tensor-core GEMM: C[M,N] = A[M,K] * B[K,N], row-major fp32 in/out.
// Split-precision: a = a_hi + a_lo (tf32 each); acc += ahi*bhi + alo*bhi
// + ahi*blo  ->  fp32-class accuracy on tensor cores.
// 128x128 CTA tile, BK=32, 256 threads = 8 warps (2x4), warp tile 64x32.
// A smem: lda=32 floats, XOR-swizzled -> conflict-free cp.async + ldmatrix.x4.
// B smem: ldb=136 floats (pad 8) -> conflict-free stores and LDS.32 reads.
// Double-buffered cp.async pipeline.
// ===========================================================================
#define BM 128
#define BN 128
#define BK 32
#define LDA 32
#define LDB 136
#define A_TILE_F (BM*LDA)                 // 4096 floats
#define B_TILE_F (BK*LDB)                 // 4352 floats
#define GEMM_SMEM_BYTES ((2*(A_TILE_F + B_TILE_F))*4)   // 67584 B

__device__ __forceinline__ void cp_async16(uint32_t dst, const void* src) {
    asm volatile("cp.async.cg.shared.global [%0], [%1], 16;\n"
                 :: "r"(dst), "l"(src));
}
__device__ __forceinline__ void cp_commit() {
    asm volatile("cp.async.commit_group;\n");
}
__device__ __forceinline__ void cp_wait1() {
    asm volatile("cp.async.wait_group 1;\n");
}
__device__ __forceinline__ void cp_wait0() {
    asm volatile("cp.async.wait_group 0;\n");
}
__device__ __forceinline__ void ldsm4(uint32_t a[4], uint32_t saddr) {
    asm volatile("ldmatrix.sync.aligned.m8n8.x4.shared.b16 {%0,%1,%2,%3}, [%4];\n"
                 : "=r"(a[0]), "=r"(a[1]), "=r"(a[2]), "=r"(a[3])
                 : "r"(saddr));
}
__device__ __forceinline__ uint32_t f2tf32(float x) {
    uint32_t r;
    asm("cvt.rna.tf32.f32 %0, %1;\n" : "=r"(r) : "f"(x));
    return r;
}
__device__ __forceinline__ void mma_tf32(float c[4], const uint32_t a[4],
                                         const uint32_t b[2]) {
    asm volatile(
        "mma.sync.aligned.m16n8k8.row.col.f32.tf32.tf32.f32 "
        "{%0,%1,%2,%3},{%4,%5,%6,%7},{%8,%9},{%0,%1,%2,%3};\n"
        : "+f"(c[0]), "+f"(c[1]), "+f"(c[2]), "+f"(c[3])
        : "r"(a[0]), "r"(a[1]), "r"(a[2]), "r"(a[3]), "r"(b[0]), "r"(b[1]));
}

__global__ void __launch_bounds__(256) gemm_tf32_kernel(
    const float* __restrict__ A, const float* __restrict__ B,
    float* __restrict__ C, int M, int N, int K)
{
    extern __shared__ float sm[];
    const int tid = threadIdx.x;
    const int bm = blockIdx.y, bn = blockIdx.x;

    float* AsBase = sm;                       // [2][A_TILE_F]
    float* BsBase = sm + 2 * A_TILE_F;        // [2][B_TILE_F]
    const uint32_t sA = (uint32_t)__cvta_generic_to_shared(AsBase);
    const uint32_t sB = (uint32_t)__cvta_generic_to_shared(BsBase);

    const float* Ag = A + (size_t)bm * BM * K;
    const float* Bg = B + (size_t)bn * BN;
    const int NT = K / BK;

    auto stage = [&](int kt, int buf) {
        uint32_t dA = sA + (uint32_t)buf * (A_TILE_F * 4);
        uint32_t dB = sB + (uint32_t)buf * (B_TILE_F * 4);
#pragma unroll
        for (int it = 0; it < 4; it++) {
            int f = it * 256 + tid;
            int r  = f >> 3, ch = f & 7;
            int chs = ch ^ (r & 7);
            cp_async16(dA + (uint32_t)(r * LDA + chs * 4) * 4,
                       Ag + (size_t)r * K + (size_t)kt * BK + ch * 4);
            int rb = f >> 5, c4 = f & 31;
            cp_async16(dB + (uint32_t)(rb * LDB + c4 * 4) * 4,
                       Bg + (size_t)(kt * BK + rb) * N + c4 * 4);
        }
    };

    stage(0, 0);
    cp_commit();

    const int warp = tid >> 5, lane = tid & 31;
    const int wm = (warp >> 2) * 64;     // warp M offset (0 or 64)
    const int wn = (warp & 3) * 32;      // warp N offset (0..96)

    float acc[4][4][4];
#pragma unroll
    for (int i = 0; i < 4; i++)
#pragma unroll
        for (int j = 0; j < 4; j++)
#pragma unroll
            for (int c = 0; c < 4; c++) acc[i][j][c] = 0.0f;

    for (int kt = 0; kt < NT; kt++) {
        const int buf = kt & 1;
        if (kt + 1 < NT) {
            stage(kt + 1, buf ^ 1);
            cp_commit();
            cp_wait1();
        } else {
            cp_wait0();
        }
        __syncthreads();

        const float* Bs = BsBase + buf * B_TILE_F;
        const uint32_t sAbuf = sA + (uint32_t)buf * (A_TILE_F * 4);

#pragma unroll
        for (int ks = 0; ks < 4; ks++) {
            // B fragments (LDS.32, padded, conflict-free), split hi/lo
            uint32_t bhi[4][2], blo[4][2];
            {
                const int r0 = ks * 8 + (lane & 3);
                const int cb = wn + (lane >> 2);
#pragma unroll
                for (int nj = 0; nj < 4; nj++) {
                    float b0 = Bs[r0 * LDB + cb + nj * 8];
                    float b1 = Bs[(r0 + 4) * LDB + cb + nj * 8];
                    bhi[nj][0] = f2tf32(b0);
                    bhi[nj][1] = f2tf32(b1);
                    blo[nj][0] = f2tf32(b0 - __uint_as_float(bhi[nj][0]));
                    blo[nj][1] = f2tf32(b1 - __uint_as_float(bhi[nj][1]));
                }
            }
#pragma unroll
            for (int mi = 0; mi < 4; mi++) {
                // A fragment via ldmatrix.x4 (swizzled), split hi/lo
                uint32_t araw[4], ahi[4], alo[4];
                {
                    int row = wm + mi * 16 + (lane & 15);
                    int ch  = ks * 2 + (lane >> 4);
                    int chs = ch ^ (row & 7);
                    ldsm4(araw, sAbuf + (uint32_t)(row * LDA + chs * 4) * 4);
                }
#pragma unroll
                for (int t = 0; t < 4; t++) {
                    float a = __uint_as_float(araw[t]);
                    ahi[t] = f2tf32(a);
                    alo[t] = f2tf32(a - __uint_as_float(ahi[t]));
                }
#pragma unroll
                for (int nj = 0; nj < 4; nj++) {
                    mma_tf32(acc[mi][nj], alo, bhi[nj]);   // correction terms
                    mma_tf32(acc[mi][nj], ahi, blo[nj]);   // first (smaller)
                    mma_tf32(acc[mi][nj], ahi, bhi[nj]);   // main term
                }
            }
        }
        __syncthreads();
    }

    // Epilogue: c0,c1 at (row, 2t..2t+1), c2,c3 at (row+8, ...)
    const int g = lane >> 2, t = lane & 3;
#pragma unroll
    for (int mi = 0; mi < 4; mi++) {
        size_t row = (size_t)bm * BM + wm + mi * 16 + g;
#pragma unroll
        for (int nj = 0; nj < 4; nj++) {
            int col = bn * BN + wn + nj * 8 + t * 2;
            *(float2*)(C + row * N + col) =
                make_float2(acc[mi][nj][0], acc[mi][nj][1]);
            *(float2*)(C + (row + 8) * N + col) =
                make_float2(acc[mi][nj][2], acc[mi][nj][3]);
        }
    }
}

// ---------------------------------------------------------------------------
// RoPE: X[4096, nH*64] in place. pair j in 0..31 per head.
// ---------------------------------------------------------------------------
__global__ void rope_kernel(float* __restrict__ X, const float* __restrict__ freq,
                            int nH, int total)
{
    int idx = blockIdx.x * blockDim.x + threadIdx.x;
    if (idx >= total) return;
    int j = idx & 31;
    int h = (idx >> 5) % nH;
    int m = idx / (32 * nH);
    int t = m & (Tt - 1);
    float c = freq[t * 64 + j * 2 + 0];
    float s = freq[t * 64 + j * 2 + 1];
    float2* p = (float2*)(X + (size_t)m * nH * 64 + h * 64 + j * 2);
    float2 ab = *p;
    float2 o;
    o.x = ab.x * c - ab.y * s;
    o.y = ab.x * s + ab.y * c;
    *p = o;
}

// ---------------------------------------------------------------------------
// Causal flash attention, GQA (kv head = h/4), fp32.  (unchanged, validated)
// ---------------------------------------------------------------------------
#define APAD 68
#define ASM_BYTES (3 * 64 * APAD * 4)

__global__ void __launch_bounds__(256) attn_kernel()
{
    extern __shared__ float smf[];
    float* Qs = smf;
    float* Ks = smf + 64 * APAD;   // reused as P after softmax
    float* Vs = smf + 2 * 64 * APAD;

    const int qt = blockIdx.x;
    const int h  = blockIdx.y;
    const int b  = blockIdx.z;
    const int kvh = h >> 2;

    const int tid = threadIdx.x;
    const int tx  = tid & 15;
    const int ty  = tid >> 4;
    const int r0  = ty * 4;
    const int c0  = tx * 4;

    const size_t qbase = ((size_t)b * Tt + (size_t)qt * 64) * QN + h * Dd;

#pragma unroll
    for (int it = 0; it < 4; it++) {
        int f = tid + it * 256;
        int row = f >> 4, c4 = (f & 15) << 2;
        *(float4*)(&Qs[row * APAD + c4]) =
            *(const float4*)(&g_Q[qbase + (size_t)row * QN + c4]);
    }

    float O[4][4];
    float mrow[4], lrow[4];
#pragma unroll
    for (int i = 0; i < 4; i++) {
        mrow[i] = -1e30f; lrow[i] = 0.0f;
#pragma unroll
        for (int j = 0; j < 4; j++) O[i][j] = 0.0f;
    }

    const float scale = 0.125f;

    for (int kt = 0; kt <= qt; kt++) {
        __syncthreads();
        const size_t kbase = ((size_t)b * Tt + (size_t)kt * 64) * KN + kvh * Dd;
#pragma unroll
        for (int it = 0; it < 4; it++) {
            int f = tid + it * 256;
            int row = f >> 4, c4 = (f & 15) << 2;
            *(float4*)(&Ks[row * APAD + c4]) =
                *(const float4*)(&g_K[kbase + (size_t)row * KN + c4]);
            *(float4*)(&Vs[row * APAD + c4]) =
                *(const float4*)(&g_V[kbase + (size_t)row * KN + c4]);
        }
        __syncthreads();

        float s[4][4];
#pragma unroll
        for (int i = 0; i < 4; i++)
#pragma unroll
            for (int j = 0; j < 4; j++) s[i][j] = 0.0f;

#pragma unroll
        for (int d = 0; d < 64; d += 4) {
            float q[4][4], k[4][4];
#pragma unroll
            for (int i = 0; i < 4; i++)
                *(float4*)(q[i]) = *(const float4*)(&Qs[(r0 + i) * APAD + d]);
#pragma unroll
            for (int j = 0; j < 4; j++)
                *(float4*)(k[j]) = *(const float4*)(&Ks[(c0 + j) * APAD + d]);
#pragma unroll
            for (int i = 0; i < 4; i++)
#pragma unroll
                for (int j = 0; j < 4; j++) {
                    s[i][j] += q[i][0] * k[j][0];
                    s[i][j] += q[i][1] * k[j][1];
                    s[i][j] += q[i][2] * k[j][2];
                    s[i][j] += q[i][3] * k[j][3];
                }
        }

        if (kt == qt) {
#pragma unroll
            for (int i = 0; i < 4; i++) {
                int qg = r0 + i;
#pragma unroll
                for (int j = 0; j < 4; j++) {
                    int kg = c0 + j;
                    s[i][j] = (kg > qg) ? -1e30f : s[i][j] * scale;
                }
            }
        } else {
#pragma unroll
            for (int i = 0; i < 4; i++)
#pragma unroll
                for (int j = 0; j < 4; j++) s[i][j] *= scale;
        }

#pragma unroll
        for (int i = 0; i < 4; i++) {
            float rmax = fmaxf(fmaxf(s[i][0], s[i][1]), fmaxf(s[i][2], s[i][3]));
#pragma unroll
            for (int msk = 8; msk >= 1; msk >>= 1)
                rmax = fmaxf(rmax, __shfl_xor_sync(0xffffffffu, rmax, msk));
            float mn = fmaxf(mrow[i], rmax);
            float alpha = __expf(mrow[i] - mn);
            mrow[i] = mn;
            float rsum = 0.0f;
#pragma unroll
            for (int j = 0; j < 4; j++) {
                float p = __expf(s[i][j] - mn);
                s[i][j] = p;
                rsum += p;
            }
#pragma unroll
            for (int msk = 8; msk >= 1; msk >>= 1)
                rsum += __shfl_xor_sync(0xffffffffu, rsum, msk);
            lrow[i] = lrow[i] * alpha + rsum;
#pragma unroll
            for (int j = 0; j < 4; j++) O[i][j] *= alpha;
        }

        __syncthreads();
#pragma unroll
        for (int i = 0; i < 4; i++)
            *(float4*)(&Ks[(r0 + i) * APAD + c0]) =
                make_float4(s[i][0], s[i][1], s[i][2], s[i][3]);
        __syncthreads();

#pragma unroll
        for (int k = 0; k < 64; k += 4) {
            float p[4][4];
#pragma unroll
            for (int i = 0; i < 4; i++)
                *(float4*)(p[i]) = *(const float4*)(&Ks[(r0 + i) * APAD + k]);
#pragma unroll
            for (int kk = 0; kk < 4; kk++) {
                float4 v = *(const float4*)(&Vs[(k + kk) * APAD + c0]);
#pragma unroll
                for (int i = 0; i < 4; i++) {
                    O[i][0] += p[i][kk] * v.x;
                    O[i][1] += p[i][kk] * v.y;
                    O[i][2] += p[i][kk] * v.z;
                    O[i][3] += p[i][kk] * v.w;
                }
            }
        }
    }

#pragma unroll
    for (int i = 0; i < 4; i++) {
        float inv = 1.0f / lrow[i];
        float4 o = make_float4(O[i][0] * inv, O[i][1] * inv,
                               O[i][2] * inv, O[i][3] * inv);
        *(float4*)(&g_O[qbase + (size_t)(r0 + i) * QN + c0]) = o;
    }
}

// ---------------------------------------------------------------------------
extern "C" void kernel_launch(void* const* d_in, const int* in_sizes, int n_in,
                              void* d_out, int out_size)
{
    const float* x    = (const float*)d_in[0];
    const float* freq = (const float*)d_in[1];
    const float* Wq   = (const float*)d_in[2];
    const float* Wk   = (const float*)d_in[3];
    const float* Wv   = (const float*)d_in[4];
    const float* Wo   = (const float*)d_in[5];
    float* out = (float*)d_out;

    void *pQ, *pK, *pV, *pO;
    cudaGetSymbolAddress(&pQ, g_Q);
    cudaGetSymbolAddress(&pK, g_K);
    cudaGetSymbolAddress(&pV, g_V);
    cudaGetSymbolAddress(&pO, g_O);

    cudaFuncSetAttribute(gemm_tf32_kernel,
                         cudaFuncAttributeMaxDynamicSharedMemorySize,
                         GEMM_SMEM_BYTES);
    cudaFuncSetAttribute(attn_kernel,
                         cudaFuncAttributeMaxDynamicSharedMemorySize, ASM_BYTES);

    // QKV projections (3xTF32 tensor cores)
    gemm_tf32_kernel<<<dim3(QN / BN, Mrows / BM), 256, GEMM_SMEM_BYTES>>>(
        x, Wq, (float*)pQ, Mrows, QN, Ee);
    gemm_tf32_kernel<<<dim3(KN / BN, Mrows / BM), 256, GEMM_SMEM_BYTES>>>(
        x, Wk, (float*)pK, Mrows, KN, Ee);
    gemm_tf32_kernel<<<dim3(KN / BN, Mrows / BM), 256, GEMM_SMEM_BYTES>>>(
        x, Wv, (float*)pV, Mrows, KN, Ee);

    // RoPE
    {
        int totQ = Mrows * Hh * 32;
        rope_kernel<<<(totQ + 255) / 256, 256>>>((float*)pQ, freq, Hh, totQ);
        int totK = Mrows * KVh * 32;
        rope_kernel<<<(totK + 255) / 256, 256>>>((float*)pK, freq, KVh, totK);
    }

    // Attention (fp32 flash, unchanged)
    attn_kernel<<<dim3(Tt / 64, Hh, Bb), 256, ASM_BYTES>>>();

    // Output projection (3xTF32 tensor cores)
    gemm_tf32_kernel<<<dim3(Ee / BN, Mrows / BM), 256, GEMM_SMEM_BYTES>>>(
        (const float*)pO, Wo, out, Mrows, Ee, QN);
}

// round 14
// speedup vs baseline: 1.3101x; 1.3101x over previous
#include <cuda_runtime.h>
#include <cuda_bf16.h>
#include <math.h>
#include <stdint.h>

// Problem constants
#define Bb  2
#define Tt  2048
#define Ee  2048
#define Hh  32
#define KVh 8
#define Dd  64
#define Mrows (Bb*Tt)          // 4096
#define QN  (Hh*Dd)            // 2048
#define KN  (KVh*Dd)           // 512

// Scratch (device globals — no allocations allowed)
__device__ float g_Q[(size_t)Mrows*QN];
__device__ float g_K[(size_t)Mrows*KN];
__device__ float g_V[(size_t)Mrows*KN];
__device__ float g_O[(size_t)Mrows*QN];

// ===========================================================================
// Shared PTX helpers
// ===========================================================================
__device__ __forceinline__ void cp_async16(uint32_t dst, const void* src) {
    asm volatile("cp.async.cg.shared.global [%0], [%1], 16;\n"
                 :: "r"(dst), "l"(src));
}
__device__ __forceinline__ void cp_commit() {
    asm volatile("cp.async.commit_group;\n");
}
__device__ __forceinline__ void cp_wait1() {
    asm volatile("cp.async.wait_group 1;\n");
}
__device__ __forceinline__ void cp_wait0() {
    asm volatile("cp.async.wait_group 0;\n");
}
__device__ __forceinline__ void ldsm4(uint32_t a[4], uint32_t saddr) {
    asm volatile("ldmatrix.sync.aligned.m8n8.x4.shared.b16 {%0,%1,%2,%3}, [%4];\n"
                 : "=r"(a[0]), "=r"(a[1]), "=r"(a[2]), "=r"(a[3])
                 : "r"(saddr));
}
__device__ __forceinline__ uint32_t f2tf32(float x) {
    uint32_t r;
    asm("cvt.rna.tf32.f32 %0, %1;\n" : "=r"(r) : "f"(x));
    return r;
}
__device__ __forceinline__ void split2(float x, uint32_t& hi, uint32_t& lo) {
    hi = f2tf32(x);
    lo = f2tf32(x - __uint_as_float(hi));
}
__device__ __forceinline__ void mma_tf32(float c[4], const uint32_t a[4],
                                         const uint32_t b[2]) {
    asm volatile(
        "mma.sync.aligned.m16n8k8.row.col.f32.tf32.tf32.f32 "
        "{%0,%1,%2,%3},{%4,%5,%6,%7},{%8,%9},{%0,%1,%2,%3};\n"
        : "+f"(c[0]), "+f"(c[1]), "+f"(c[2]), "+f"(c[3])
        : "r"(a[0]), "r"(a[1]), "r"(a[2]), "r"(a[3]), "r"(b[0]), "r"(b[1]));
}

// ===========================================================================
// 3xTF32 tensor-core GEMM (unchanged from R12, passing @ rel_err 4.3e-5)
// ===========================================================================
#define BM 128
#define BN 128
#define BK 32
#define LDA 32
#define LDB 136
#define A_TILE_F (BM*LDA)
#define B_TILE_F (BK*LDB)
#define GEMM_SMEM_BYTES ((2*(A_TILE_F + B_TILE_F))*4)

__global__ void __launch_bounds__(256) gemm_tf32_kernel(
    const float* __restrict__ A, const float* __restrict__ B,
    float* __restrict__ C, int M, int N, int K)
{
    extern __shared__ float sm[];
    const int tid = threadIdx.x;
    const int bm = blockIdx.y, bn = blockIdx.x;

    float* AsBase = sm;
    float* BsBase = sm + 2 * A_TILE_F;
    const uint32_t sA = (uint32_t)__cvta_generic_to_shared(AsBase);
    const uint32_t sB = (uint32_t)__cvta_generic_to_shared(BsBase);

    const float* Ag = A + (size_t)bm * BM * K;
    const float* Bg = B + (size_t)bn * BN;
    const int NT = K / BK;

    auto stage = [&](int kt, int buf) {
        uint32_t dA = sA + (uint32_t)buf * (A_TILE_F * 4);
        uint32_t dB = sB + (uint32_t)buf * (B_TILE_F * 4);
#pragma unroll
        for (int it = 0; it < 4; it++) {
            int f = it * 256 + tid;
            int r  = f >> 3, ch = f & 7;
            int chs = ch ^ (r & 7);
            cp_async16(dA + (uint32_t)(r * LDA + chs * 4) * 4,
                       Ag + (size_t)r * K + (size_t)kt * BK + ch * 4);
            int rb = f >> 5, c4 = f & 31;
            cp_async16(dB + (uint32_t)(rb * LDB + c4 * 4) * 4,
                       Bg + (size_t)(kt * BK + rb) * N + c4 * 4);
        }
    };

    stage(0, 0);
    cp_commit();

    const int warp = tid >> 5, lane = tid & 31;
    const int wm = (warp >> 2) * 64;
    const int wn = (warp & 3) * 32;

    float acc[4][4][4];
#pragma unroll
    for (int i = 0; i < 4; i++)
#pragma unroll
        for (int j = 0; j < 4; j++)
#pragma unroll
            for (int c = 0; c < 4; c++) acc[i][j][c] = 0.0f;

    for (int kt = 0; kt < NT; kt++) {
        const int buf = kt & 1;
        if (kt + 1 < NT) {
            stage(kt + 1, buf ^ 1);
            cp_commit();
            cp_wait1();
        } else {
            cp_wait0();
        }
        __syncthreads();

        const float* Bs = BsBase + buf * B_TILE_F;
        const uint32_t sAbuf = sA + (uint32_t)buf * (A_TILE_F * 4);

#pragma unroll
        for (int ks = 0; ks < 4; ks++) {
            uint32_t bhi[4][2], blo[4][2];
            {
                const int r0 = ks * 8 + (lane & 3);
                const int cb = wn + (lane >> 2);
#pragma unroll
                for (int nj = 0; nj < 4; nj++) {
                    float b0 = Bs[r0 * LDB + cb + nj * 8];
                    float b1 = Bs[(r0 + 4) * LDB + cb + nj * 8];
                    split2(b0, bhi[nj][0], blo[nj][0]);
                    split2(b1, bhi[nj][1], blo[nj][1]);
                }
            }
#pragma unroll
            for (int mi = 0; mi < 4; mi++) {
                uint32_t araw[4], ahi[4], alo[4];
                {
                    int row = wm + mi * 16 + (lane & 15);
                    int ch  = ks * 2 + (lane >> 4);
                    int chs = ch ^ (row & 7);
                    ldsm4(araw, sAbuf + (uint32_t)(row * LDA + chs * 4) * 4);
                }
#pragma unroll
                for (int t = 0; t < 4; t++)
                    split2(__uint_as_float(araw[t]), ahi[t], alo[t]);
#pragma unroll
                for (int nj = 0; nj < 4; nj++) {
                    mma_tf32(acc[mi][nj], alo, bhi[nj]);
                    mma_tf32(acc[mi][nj], ahi, blo[nj]);
                    mma_tf32(acc[mi][nj], ahi, bhi[nj]);
                }
            }
        }
        __syncthreads();
    }

    const int g = lane >> 2, t = lane & 3;
#pragma unroll
    for (int mi = 0; mi < 4; mi++) {
        size_t row = (size_t)bm * BM + wm + mi * 16 + g;
#pragma unroll
        for (int nj = 0; nj < 4; nj++) {
            int col = bn * BN + wn + nj * 8 + t * 2;
            *(float2*)(C + row * N + col) =
                make_float2(acc[mi][nj][0], acc[mi][nj][1]);
            *(float2*)(C + (row + 8) * N + col) =
                make_float2(acc[mi][nj][2], acc[mi][nj][3]);
        }
    }
}

// ---------------------------------------------------------------------------
// RoPE (unchanged)
// ---------------------------------------------------------------------------
__global__ void rope_kernel(float* __restrict__ X, const float* __restrict__ freq,
                            int nH, int total)
{
    int idx = blockIdx.x * blockDim.x + threadIdx.x;
    if (idx >= total) return;
    int j = idx & 31;
    int h = (idx >> 5) % nH;
    int m = idx / (32 * nH);
    int t = m & (Tt - 1);
    float c = freq[t * 64 + j * 2 + 0];
    float s = freq[t * 64 + j * 2 + 1];
    float2* p = (float2*)(X + (size_t)m * nH * 64 + h * 64 + j * 2);
    float2 ab = *p;
    float2 o;
    o.x = ab.x * c - ab.y * s;
    o.y = ab.x * s + ab.y * c;
    *p = o;
}

// ===========================================================================
// Tensor-core causal flash attention (3xTF32), GQA kv = h/4.
// Grid (T/64, H, B), 256 threads = 8 warps: warp = 4(M-groups of 16 rows)
// x 2(col-halves of 32). Per warp: mi=1, nj=4 fragments.
// All fragment loads are plain LDS.32, conflict-free by pitch choice:
//   A-side pitch 68 floats: bank = 4*(lane>>2) + (lane&3)  (bijective)
//   B-side pitch 72 floats: bank = 8*x + y                 (bijective)
// smem: Qs[64*68] Ks[64*72] Vs[64*72] Ps[64*68] redm[128] reds[128]
// ===========================================================================
#define LQ 68
#define LK 72
#define OFF_K 4352
#define OFF_V 8960
#define OFF_P 13568
#define OFF_RM 17920
#define OFF_RS 18048
#define ASM_BYTES (18176 * 4)

__global__ void __launch_bounds__(256) attn_kernel()
{
    extern __shared__ float smf[];
    float* Qs = smf;
    float* Ks = smf + OFF_K;
    float* Vs = smf + OFF_V;
    float* Ps = smf + OFF_P;
    float* redm = smf + OFF_RM;   // [2][64] row maxima
    float* reds = smf + OFF_RS;   // [2][64] row sums

    const int qt = blockIdx.x;
    const int h  = blockIdx.y;
    const int b  = blockIdx.z;
    const int kvh = h >> 2;

    const int tid  = threadIdx.x;
    const int warp = tid >> 5, lane = tid & 31;
    const int g = lane >> 2, t = lane & 3;
    const int wm = (warp >> 1) * 16;       // row group
    const int side = warp & 1;
    const int wn = side * 32;              // col half (S cols / O d-cols)
    const int rA = wm + g, rB = wm + g + 8;

    const size_t qbase = ((size_t)b * Tt + (size_t)qt * 64) * QN + h * Dd;

    // Load Q tile (64x64), pre-scaled by 1/sqrt(D)
#pragma unroll
    for (int it = 0; it < 4; it++) {
        int f = tid + it * 256;
        int row = f >> 4, c4 = (f & 15) << 2;
        float4 qv = *(const float4*)(&g_Q[qbase + (size_t)row * QN + c4]);
        qv.x *= 0.125f; qv.y *= 0.125f; qv.z *= 0.125f; qv.w *= 0.125f;
        *(float4*)(&Qs[row * LQ + c4]) = qv;
    }

    float oacc[4][4];
    float mA = -1e30f, mB = -1e30f, lA = 0.0f, lB = 0.0f;
#pragma unroll
    for (int nj = 0; nj < 4; nj++)
#pragma unroll
        for (int c = 0; c < 4; c++) oacc[nj][c] = 0.0f;

    for (int kt = 0; kt <= qt; kt++) {
        __syncthreads();   // protect Ks/Vs/Ps from previous iteration readers
        const size_t kbase = ((size_t)b * Tt + (size_t)kt * 64) * KN + kvh * Dd;
#pragma unroll
        for (int it = 0; it < 4; it++) {
            int f = tid + it * 256;
            int row = f >> 4, c4 = (f & 15) << 2;
            *(float4*)(&Ks[row * LK + c4]) =
                *(const float4*)(&g_K[kbase + (size_t)row * KN + c4]);
            *(float4*)(&Vs[row * LK + c4]) =
                *(const float4*)(&g_V[kbase + (size_t)row * KN + c4]);
        }
        __syncthreads();

        // ---- S = Q K^T (3xTF32) ----
        float sacc[4][4];
#pragma unroll
        for (int nj = 0; nj < 4; nj++)
#pragma unroll
            for (int c = 0; c < 4; c++) sacc[nj][c] = 0.0f;

#pragma unroll
        for (int ks = 0; ks < 8; ks++) {
            uint32_t ahi[4], alo[4];
            {
                const float* q0 = &Qs[rA * LQ + ks * 8 + t];
                const float* q1 = &Qs[rB * LQ + ks * 8 + t];
                split2(q0[0], ahi[0], alo[0]);
                split2(q1[0], ahi[1], alo[1]);
                split2(q0[4], ahi[2], alo[2]);
                split2(q1[4], ahi[3], alo[3]);
            }
#pragma unroll
            for (int nj = 0; nj < 4; nj++) {
                uint32_t bhi[2], blo[2];
                const float* kp = &Ks[(wn + nj * 8 + g) * LK + ks * 8 + t];
                split2(kp[0], bhi[0], blo[0]);
                split2(kp[4], bhi[1], blo[1]);
                mma_tf32(sacc[nj], alo, bhi);
                mma_tf32(sacc[nj], ahi, blo);
                mma_tf32(sacc[nj], ahi, bhi);
            }
        }

        // ---- causal mask on diagonal tile ----
        if (kt == qt) {
#pragma unroll
            for (int nj = 0; nj < 4; nj++) {
                int kc = wn + nj * 8 + 2 * t;
                if (kc     > rA) sacc[nj][0] = -1e30f;
                if (kc + 1 > rA) sacc[nj][1] = -1e30f;
                if (kc     > rB) sacc[nj][2] = -1e30f;
                if (kc + 1 > rB) sacc[nj][3] = -1e30f;
            }
        }

        // ---- online softmax ----
        float lmA = -1e30f, lmB = -1e30f;
#pragma unroll
        for (int nj = 0; nj < 4; nj++) {
            lmA = fmaxf(lmA, fmaxf(sacc[nj][0], sacc[nj][1]));
            lmB = fmaxf(lmB, fmaxf(sacc[nj][2], sacc[nj][3]));
        }
        lmA = fmaxf(lmA, __shfl_xor_sync(0xffffffffu, lmA, 1));
        lmA = fmaxf(lmA, __shfl_xor_sync(0xffffffffu, lmA, 2));
        lmB = fmaxf(lmB, __shfl_xor_sync(0xffffffffu, lmB, 1));
        lmB = fmaxf(lmB, __shfl_xor_sync(0xffffffffu, lmB, 2));
        if (t == 0) {
            redm[side * 64 + rA] = lmA;
            redm[side * 64 + rB] = lmB;
        }
        __syncthreads();
        float gmA = fmaxf(redm[rA], redm[64 + rA]);
        float gmB = fmaxf(redm[rB], redm[64 + rB]);
        float nmA = fmaxf(mA, gmA), nmB = fmaxf(mB, gmB);
        float alA = __expf(mA - nmA), alB = __expf(mB - nmB);
        mA = nmA; mB = nmB;

        float lsA = 0.0f, lsB = 0.0f;
#pragma unroll
        for (int nj = 0; nj < 4; nj++) {
            float p0 = __expf(sacc[nj][0] - nmA);
            float p1 = __expf(sacc[nj][1] - nmA);
            float p2 = __expf(sacc[nj][2] - nmB);
            float p3 = __expf(sacc[nj][3] - nmB);
            lsA += p0 + p1; lsB += p2 + p3;
            int col = wn + nj * 8 + 2 * t;
            *(float2*)(&Ps[rA * LQ + col]) = make_float2(p0, p1);
            *(float2*)(&Ps[rB * LQ + col]) = make_float2(p2, p3);
        }
        lsA += __shfl_xor_sync(0xffffffffu, lsA, 1);
        lsA += __shfl_xor_sync(0xffffffffu, lsA, 2);
        lsB += __shfl_xor_sync(0xffffffffu, lsB, 1);
        lsB += __shfl_xor_sync(0xffffffffu, lsB, 2);
        if (t == 0) {
            reds[side * 64 + rA] = lsA;
            reds[side * 64 + rB] = lsB;
        }

        // rescale O while waiting
#pragma unroll
        for (int nj = 0; nj < 4; nj++) {
            oacc[nj][0] *= alA; oacc[nj][1] *= alA;
            oacc[nj][2] *= alB; oacc[nj][3] *= alB;
        }
        __syncthreads();
        lA = lA * alA + reds[rA] + reds[64 + rA];
        lB = lB * alB + reds[rB] + reds[64 + rB];

        // ---- O += P V (3xTF32) ----
#pragma unroll
        for (int ks = 0; ks < 8; ks++) {
            uint32_t ahi[4], alo[4];
            {
                const float* p0 = &Ps[rA * LQ + ks * 8 + t];
                const float* p1 = &Ps[rB * LQ + ks * 8 + t];
                split2(p0[0], ahi[0], alo[0]);
                split2(p1[0], ahi[1], alo[1]);
                split2(p0[4], ahi[2], alo[2]);
                split2(p1[4], ahi[3], alo[3]);
            }
#pragma unroll
            for (int nj = 0; nj < 4; nj++) {
                uint32_t bhi[2], blo[2];
                const float* vp = &Vs[(ks * 8 + t) * LK + wn + nj * 8 + g];
                split2(vp[0],      bhi[0], blo[0]);
                split2(vp[4 * LK], bhi[1], blo[1]);
                mma_tf32(oacc[nj], alo, bhi);
                mma_tf32(oacc[nj], ahi, blo);
                mma_tf32(oacc[nj], ahi, bhi);
            }
        }
    }

    // Normalize + write out
    float invA = 1.0f / lA, invB = 1.0f / lB;
#pragma unroll
    for (int nj = 0; nj < 4; nj++) {
        int col = wn + nj * 8 + 2 * t;
        *(float2*)(&g_O[qbase + (size_t)rA * QN + col]) =
            make_float2(oacc[nj][0] * invA, oacc[nj][1] * invA);
        *(float2*)(&g_O[qbase + (size_t)rB * QN + col]) =
            make_float2(oacc[nj][2] * invB, oacc[nj][3] * invB);
    }
}

// ---------------------------------------------------------------------------
extern "C" void kernel_launch(void* const* d_in, const int* in_sizes, int n_in,
                              void* d_out, int out_size)
{
    const float* x    = (const float*)d_in[0];
    const float* freq = (const float*)d_in[1];
    const float* Wq   = (const float*)d_in[2];
    const float* Wk   = (const float*)d_in[3];
    const float* Wv   = (const float*)d_in[4];
    const float* Wo   = (const float*)d_in[5];
    float* out = (float*)d_out;

    void *pQ, *pK, *pV, *pO;
    cudaGetSymbolAddress(&pQ, g_Q);
    cudaGetSymbolAddress(&pK, g_K);
    cudaGetSymbolAddress(&pV, g_V);
    cudaGetSymbolAddress(&pO, g_O);

    cudaFuncSetAttribute(gemm_tf32_kernel,
                         cudaFuncAttributeMaxDynamicSharedMemorySize,
                         GEMM_SMEM_BYTES);
    cudaFuncSetAttribute(attn_kernel,
                         cudaFuncAttributeMaxDynamicSharedMemorySize, ASM_BYTES);

    // QKV projections (3xTF32 tensor cores)
    gemm_tf32_kernel<<<dim3(QN / BN, Mrows / BM), 256, GEMM_SMEM_BYTES>>>(
        x, Wq, (float*)pQ, Mrows, QN, Ee);
    gemm_tf32_kernel<<<dim3(KN / BN, Mrows / BM), 256, GEMM_SMEM_BYTES>>>(
        x, Wk, (float*)pK, Mrows, KN, Ee);
    gemm_tf32_kernel<<<dim3(KN / BN, Mrows / BM), 256, GEMM_SMEM_BYTES>>>(
        x, Wv, (float*)pV, Mrows, KN, Ee);

    // RoPE
    {
        int totQ = Mrows * Hh * 32;
        rope_kernel<<<(totQ + 255) / 256, 256>>>((float*)pQ, freq, Hh, totQ);
        int totK = Mrows * KVh * 32;
        rope_kernel<<<(totK + 255) / 256, 256>>>((float*)pK, freq, KVh, totK);
    }

    // Attention (3xTF32 tensor-core flash)
    attn_kernel<<<dim3(Tt / 64, Hh, Bb), 256, ASM_BYTES>>>();

    // Output projection (3xTF32 tensor cores)
    gemm_tf32_kernel<<<dim3(Ee / BN, Mrows / BM), 256, GEMM_SMEM_BYTES>>>(
        (const float*)pO, Wo, out, Mrows, Ee, QN);
}

// round 17
// speedup vs baseline: 1.8526x; 1.4141x over previous
#include <cuda_runtime.h>
#include <cuda_bf16.h>
#include <math.h>
#include <stdint.h>

// Problem constants
#define Bb  2
#define Tt  2048
#define Ee  2048
#define Hh  32
#define KVh 8
#define Dd  64
#define Mrows (Bb*Tt)          // 4096
#define QN  (Hh*Dd)            // 2048
#define KN  (KVh*Dd)           // 512

// Scratch (device globals — no allocations allowed)
__device__ float g_Q[(size_t)Mrows*QN];
__device__ float g_K[(size_t)Mrows*KN];
__device__ float g_V[(size_t)Mrows*KN];
__device__ float g_O[(size_t)Mrows*QN];

// ===========================================================================
// PTX helpers
// ===========================================================================
__device__ __forceinline__ void cp_async16(uint32_t dst, const void* src) {
    asm volatile("cp.async.cg.shared.global [%0], [%1], 16;\n"
                 :: "r"(dst), "l"(src));
}
__device__ __forceinline__ void cp_commit() {
    asm volatile("cp.async.commit_group;\n");
}
__device__ __forceinline__ void cp_wait1() {
    asm volatile("cp.async.wait_group 1;\n");
}
__device__ __forceinline__ void cp_wait0() {
    asm volatile("cp.async.wait_group 0;\n");
}
__device__ __forceinline__ uint32_t f2tf32(float x) {
    uint32_t r;
    asm("cvt.rna.tf32.f32 %0, %1;\n" : "=r"(r) : "f"(x));
    return r;
}
__device__ __forceinline__ void split2(float x, uint32_t& hi, uint32_t& lo) {
    hi = f2tf32(x);
    lo = f2tf32(x - __uint_as_float(hi));
}
__device__ __forceinline__ void mma_tf32(float c[4], const uint32_t a[4],
                                         const uint32_t b[2]) {
    asm volatile(
        "mma.sync.aligned.m16n8k8.row.col.f32.tf32.tf32.f32 "
        "{%0,%1,%2,%3},{%4,%5,%6,%7},{%8,%9},{%0,%1,%2,%3};\n"
        : "+f"(c[0]), "+f"(c[1]), "+f"(c[2]), "+f"(c[3])
        : "r"(a[0]), "r"(a[1]), "r"(a[2]), "r"(a[3]), "r"(b[0]), "r"(b[1]));
}
__device__ __forceinline__ void mma_bf16(float c[4], const uint32_t a[4],
                                         const uint32_t b[2]) {
    asm volatile(
        "mma.sync.aligned.m16n8k16.row.col.f32.bf16.bf16.f32 "
        "{%0,%1,%2,%3},{%4,%5,%6,%7},{%8,%9},{%0,%1,%2,%3};\n"
        : "+f"(c[0]), "+f"(c[1]), "+f"(c[2]), "+f"(c[3])
        : "r"(a[0]), "r"(a[1]), "r"(a[2]), "r"(a[3]), "r"(b[0]), "r"(b[1]));
}
__device__ __forceinline__ void ldsm4(uint32_t a[4], uint32_t saddr) {
    asm volatile("ldmatrix.sync.aligned.m8n8.x4.shared.b16 {%0,%1,%2,%3}, [%4];\n"
                 : "=r"(a[0]), "=r"(a[1]), "=r"(a[2]), "=r"(a[3])
                 : "r"(saddr));
}
__device__ __forceinline__ void ldsm4t(uint32_t a[4], uint32_t saddr) {
    asm volatile("ldmatrix.sync.aligned.m8n8.x4.trans.shared.b16 {%0,%1,%2,%3}, [%4];\n"
                 : "=r"(a[0]), "=r"(a[1]), "=r"(a[2]), "=r"(a[3])
                 : "r"(saddr));
}
// pack two floats -> bf16x2 (x0 -> low half, x1 -> high half)
__device__ __forceinline__ uint32_t packbf2(float x0, float x1) {
    uint32_t r;
    asm("cvt.rn.bf16x2.f32 %0, %1, %2;\n" : "=r"(r) : "f"(x1), "f"(x0));
    return r;
}
// split 4 consecutive floats into bf16 hi-pair and lo-pair regs
__device__ __forceinline__ void split4_bf16(const float* x,
                                            uint32_t& h01, uint32_t& h23,
                                            uint32_t& l01, uint32_t& l23) {
    h01 = packbf2(x[0], x[1]);
    h23 = packbf2(x[2], x[3]);
    float r0 = x[0] - __uint_as_float(h01 << 16);
    float r1 = x[1] - __uint_as_float(h01 & 0xffff0000u);
    float r2 = x[2] - __uint_as_float(h23 << 16);
    float r3 = x[3] - __uint_as_float(h23 & 0xffff0000u);
    l01 = packbf2(r0, r1);
    l23 = packbf2(r2, r3);
}

// ===========================================================================
// Split-BF16 (3-term) tensor-core GEMM: C[M,N] = A[M,K]*B[K,N], fp32 in/out.
// 128x128 CTA tile, BK=32, 256 threads = 8 warps (2x4), warp tile 64x32.
// Staging: cp.async fp32 -> Atmp/Btmp (double-buffered), then split into
// bf16 hi/lo tiles (single-buffered):
//   A tiles [128m][32k] bf16, pitch 64B, chunk swizzle ch ^= (m>>1)&3
//   B tiles [32k][128n] bf16, pitch 256B, chunk swizzle chn ^= k&7
// Mainloop: ldmatrix.x4 (A) / ldmatrix.x4.trans (B) + m16n8k16 bf16 mma,
// 3 terms: alo*bhi + ahi*blo + ahi*bhi (alo*blo dropped, ~2^-16 rel).
// ===========================================================================
#define SPL_AHI 1024
#define SPL_ALO (SPL_AHI + 8192)
#define SPL_BHI (SPL_AHI + 16384)
#define SPL_BLO (SPL_AHI + 24576)
#define ATMP(b) (33792 + (b) * 16384)
#define BTMP(b) (66560 + (b) * 16384)
#define GEMM_SMEM_BYTES 99328

__global__ void __launch_bounds__(256) gemm_bf16s_kernel(
    const float* __restrict__ A, const float* __restrict__ B,
    float* __restrict__ C, int M, int N, int K)
{
    extern __shared__ char smc[];
    const uint32_t sb = (uint32_t)__cvta_generic_to_shared(smc);
    const int tid = threadIdx.x;
    const int warp = tid >> 5, lane = tid & 31;
    const int bm = blockIdx.y, bn = blockIdx.x;

    const float* Ag = A + (size_t)bm * 128 * K;
    const float* Bg = B + (size_t)bn * 128;
    const int NT = K / 32;

    // cp.async staging of raw fp32 tiles
    auto stage_raw = [&](int kt, int b) {
        uint32_t dA = sb + ATMP(b);
        uint32_t dB = sb + BTMP(b);
#pragma unroll
        for (int i = 0; i < 4; i++) {
            int u = tid + i * 256;
            // A: 128 rows x 8 chunks (16B), linear pitch 32 floats
            int r = u >> 3, ch = u & 7;
            cp_async16(dA + (uint32_t)(r * 32 + ch * 4) * 4,
                       Ag + (size_t)r * K + (size_t)kt * 32 + ch * 4);
            // B: 32 k-rows x 32 chunks (16B), linear pitch 128 floats
            int k = u >> 5, c = u & 31;
            cp_async16(dB + (uint32_t)(k * 128 + c * 4) * 4,
                       Bg + (size_t)(kt * 32 + k) * N + c * 4);
        }
    };

    stage_raw(0, 0);
    cp_commit();

    const int wm = (warp >> 2) * 64;     // warp M offset (0 or 64)
    const int wn = (warp & 3) * 32;      // warp N offset (0..96)

    float acc[4][4][4];
#pragma unroll
    for (int i = 0; i < 4; i++)
#pragma unroll
        for (int j = 0; j < 4; j++)
#pragma unroll
            for (int c = 0; c < 4; c++) acc[i][j][c] = 0.0f;

    for (int kt = 0; kt < NT; kt++) {
        const int buf = kt & 1;
        if (kt + 1 < NT) {
            stage_raw(kt + 1, buf ^ 1);
            cp_commit();
            cp_wait1();
        } else {
            cp_wait0();
        }
        __syncthreads();   // prior MMA done reading split tiles; tmp[buf] visible

        // --- split A: Atmp[buf] -> Ahi/Alo bf16 tiles ---
        {
            const float* at = (const float*)(smc + ATMP(buf));
#pragma unroll
            for (int i = 0; i < 4; i++) {
                int u = tid + i * 256;          // 1024 tasks: (m, sub of 4k)
                int m = u >> 3, sub = u & 7;
                float x[4];
                *(float4*)x = *(const float4*)(at + m * 32 + sub * 4);
                uint32_t h01, h23, l01, l23;
                split4_bf16(x, h01, h23, l01, l23);
                int ch = sub >> 1, half = sub & 1;
                uint32_t off = (uint32_t)(m * 64 +
                               ((ch ^ ((m >> 1) & 3)) * 16) + half * 8);
                asm volatile("st.shared.v2.b32 [%0], {%1,%2};\n"
                    :: "r"(sb + SPL_AHI + off), "r"(h01), "r"(h23) : "memory");
                asm volatile("st.shared.v2.b32 [%0], {%1,%2};\n"
                    :: "r"(sb + SPL_ALO + off), "r"(l01), "r"(l23) : "memory");
            }
        }
        // --- split B: Btmp[buf] -> Bhi/Blo bf16 tiles ([k][n], pitch 256B) ---
        {
            const float* bt = (const float*)(smc + BTMP(buf));
#pragma unroll
            for (int i = 0; i < 4; i++) {
                int u = tid + i * 256;          // 1024 tasks: (k, sub of 4n)
                int k = u >> 5, sub = u & 31;
                float x[4];
                *(float4*)x = *(const float4*)(bt + k * 128 + sub * 4);
                uint32_t h01, h23, l01, l23;
                split4_bf16(x, h01, h23, l01, l23);
                int chn = sub >> 1, half = sub & 1;
                uint32_t off = (uint32_t)(k * 256 +
                               ((chn ^ (k & 7)) * 16) + half * 8);
                asm volatile("st.shared.v2.b32 [%0], {%1,%2};\n"
                    :: "r"(sb + SPL_BHI + off), "r"(h01), "r"(h23) : "memory");
                asm volatile("st.shared.v2.b32 [%0], {%1,%2};\n"
                    :: "r"(sb + SPL_BLO + off), "r"(l01), "r"(l23) : "memory");
            }
        }
        __syncthreads();

        // --- MMA mainloop: 2 k-steps of 16 ---
#pragma unroll
        for (int ks = 0; ks < 2; ks++) {
            // B fragments: 2 x ldmatrix.x4.trans per split (nj pairs)
            uint32_t bhi[4][2], blo[4][2];
#pragma unroll
            for (int p = 0; p < 2; p++) {
                int k_l = ks * 16 + (lane & 15);
                int chn = (wn >> 3) + 2 * p + (lane >> 4);
                uint32_t addr = (uint32_t)(k_l * 256 +
                                ((chn ^ (k_l & 7)) * 16));
                uint32_t r4[4];
                ldsm4t(r4, sb + SPL_BHI + addr);
                bhi[2*p][0] = r4[0]; bhi[2*p][1] = r4[1];
                bhi[2*p+1][0] = r4[2]; bhi[2*p+1][1] = r4[3];
                ldsm4t(r4, sb + SPL_BLO + addr);
                blo[2*p][0] = r4[0]; blo[2*p][1] = r4[1];
                blo[2*p+1][0] = r4[2]; blo[2*p+1][1] = r4[3];
            }
#pragma unroll
            for (int mi = 0; mi < 4; mi++) {
                int m_l = wm + mi * 16 + (lane & 15);
                int ch  = 2 * ks + (lane >> 4);
                uint32_t addr = (uint32_t)(m_l * 64 +
                                ((ch ^ ((m_l >> 1) & 3)) * 16));
                uint32_t ahi[4], alo[4];
                ldsm4(ahi, sb + SPL_AHI + addr);
                ldsm4(alo, sb + SPL_ALO + addr);
#pragma unroll
                for (int nj = 0; nj < 4; nj++) {
                    mma_bf16(acc[mi][nj], alo, bhi[nj]);
                    mma_bf16(acc[mi][nj], ahi, blo[nj]);
                    mma_bf16(acc[mi][nj], ahi, bhi[nj]);
                }
            }
        }
    }

    // Epilogue (same d-frag layout as before)
    const int g = lane >> 2, t = lane & 3;
#pragma unroll
    for (int mi = 0; mi < 4; mi++) {
        size_t row = (size_t)bm * 128 + wm + mi * 16 + g;
#pragma unroll
        for (int nj = 0; nj < 4; nj++) {
            int col = bn * 128 + wn + nj * 8 + t * 2;
            *(float2*)(C + row * N + col) =
                make_float2(acc[mi][nj][0], acc[mi][nj][1]);
            *(float2*)(C + (row + 8) * N + col) =
                make_float2(acc[mi][nj][2], acc[mi][nj][3]);
        }
    }
}

// ---------------------------------------------------------------------------
// RoPE (unchanged)
// ---------------------------------------------------------------------------
__global__ void rope_kernel(float* __restrict__ X, const float* __restrict__ freq,
                            int nH, int total)
{
    int idx = blockIdx.x * blockDim.x + threadIdx.x;
    if (idx >= total) return;
    int j = idx & 31;
    int h = (idx >> 5) % nH;
    int m = idx / (32 * nH);
    int t = m & (Tt - 1);
    float c = freq[t * 64 + j * 2 + 0];
    float s = freq[t * 64 + j * 2 + 1];
    float2* p = (float2*)(X + (size_t)m * nH * 64 + h * 64 + j * 2);
    float2 ab = *p;
    float2 o;
    o.x = ab.x * c - ab.y * s;
    o.y = ab.x * s + ab.y * c;
    *p = o;
}

// ===========================================================================
// Tensor-core causal flash attention (3xTF32 HMMA) — unchanged (validated)
// ===========================================================================
#define LQ 68
#define LK 72
#define OFF_K 4352
#define OFF_V 8960
#define OFF_P 13568
#define OFF_RM 17920
#define OFF_RS 18048
#define ASM_BYTES (18176 * 4)

__global__ void __launch_bounds__(256) attn_kernel()
{
    extern __shared__ float smf[];
    float* Qs = smf;
    float* Ks = smf + OFF_K;
    float* Vs = smf + OFF_V;
    float* Ps = smf + OFF_P;
    float* redm = smf + OFF_RM;
    float* reds = smf + OFF_RS;

    const int qt = blockIdx.x;
    const int h  = blockIdx.y;
    const int b  = blockIdx.z;
    const int kvh = h >> 2;

    const int tid  = threadIdx.x;
    const int warp = tid >> 5, lane = tid & 31;
    const int g = lane >> 2, t = lane & 3;
    const int wm = (warp >> 1) * 16;
    const int side = warp & 1;
    const int wn = side * 32;
    const int rA = wm + g, rB = wm + g + 8;

    const size_t qbase = ((size_t)b * Tt + (size_t)qt * 64) * QN + h * Dd;

#pragma unroll
    for (int it = 0; it < 4; it++) {
        int f = tid + it * 256;
        int row = f >> 4, c4 = (f & 15) << 2;
        float4 qv = *(const float4*)(&g_Q[qbase + (size_t)row * QN + c4]);
        qv.x *= 0.125f; qv.y *= 0.125f; qv.z *= 0.125f; qv.w *= 0.125f;
        *(float4*)(&Qs[row * LQ + c4]) = qv;
    }

    float oacc[4][4];
    float mA = -1e30f, mB = -1e30f, lA = 0.0f, lB = 0.0f;
#pragma unroll
    for (int nj = 0; nj < 4; nj++)
#pragma unroll
        for (int c = 0; c < 4; c++) oacc[nj][c] = 0.0f;

    for (int kt = 0; kt <= qt; kt++) {
        __syncthreads();
        const size_t kbase = ((size_t)b * Tt + (size_t)kt * 64) * KN + kvh * Dd;
#pragma unroll
        for (int it = 0; it < 4; it++) {
            int f = tid + it * 256;
            int row = f >> 4, c4 = (f & 15) << 2;
            *(float4*)(&Ks[row * LK + c4]) =
                *(const float4*)(&g_K[kbase + (size_t)row * KN + c4]);
            *(float4*)(&Vs[row * LK + c4]) =
                *(const float4*)(&g_V[kbase + (size_t)row * KN + c4]);
        }
        __syncthreads();

        float sacc[4][4];
#pragma unroll
        for (int nj = 0; nj < 4; nj++)
#pragma unroll
            for (int c = 0; c < 4; c++) sacc[nj][c] = 0.0f;

#pragma unroll
        for (int ks = 0; ks < 8; ks++) {
            uint32_t ahi[4], alo[4];
            {
                const float* q0 = &Qs[rA * LQ + ks * 8 + t];
                const float* q1 = &Qs[rB * LQ + ks * 8 + t];
                split2(q0[0], ahi[0], alo[0]);
                split2(q1[0], ahi[1], alo[1]);
                split2(q0[4], ahi[2], alo[2]);
                split2(q1[4], ahi[3], alo[3]);
            }
#pragma unroll
            for (int nj = 0; nj < 4; nj++) {
                uint32_t bhi[2], blo[2];
                const float* kp = &Ks[(wn + nj * 8 + g) * LK + ks * 8 + t];
                split2(kp[0], bhi[0], blo[0]);
                split2(kp[4], bhi[1], blo[1]);
                mma_tf32(sacc[nj], alo, bhi);
                mma_tf32(sacc[nj], ahi, blo);
                mma_tf32(sacc[nj], ahi, bhi);
            }
        }

        if (kt == qt) {
#pragma unroll
            for (int nj = 0; nj < 4; nj++) {
                int kc = wn + nj * 8 + 2 * t;
                if (kc     > rA) sacc[nj][0] = -1e30f;
                if (kc + 1 > rA) sacc[nj][1] = -1e30f;
                if (kc     > rB) sacc[nj][2] = -1e30f;
                if (kc + 1 > rB) sacc[nj][3] = -1e30f;
            }
        }

        float lmA = -1e30f, lmB = -1e30f;
#pragma unroll
        for (int nj = 0; nj < 4; nj++) {
            lmA = fmaxf(lmA, fmaxf(sacc[nj][0], sacc[nj][1]));
            lmB = fmaxf(lmB, fmaxf(sacc[nj][2], sacc[nj][3]));
        }
        lmA = fmaxf(lmA, __shfl_xor_sync(0xffffffffu, lmA, 1));
        lmA = fmaxf(lmA, __shfl_xor_sync(0xffffffffu, lmA, 2));
        lmB = fmaxf(lmB, __shfl_xor_sync(0xffffffffu, lmB, 1));
        lmB = fmaxf(lmB, __shfl_xor_sync(0xffffffffu, lmB, 2));
        if (t == 0) {
            redm[side * 64 + rA] = lmA;
            redm[side * 64 + rB] = lmB;
        }
        __syncthreads();
        float gmA = fmaxf(redm[rA], redm[64 + rA]);
        float gmB = fmaxf(redm[rB], redm[64 + rB]);
        float nmA = fmaxf(mA, gmA), nmB = fmaxf(mB, gmB);
        float alA = __expf(mA - nmA), alB = __expf(mB - nmB);
        mA = nmA; mB = nmB;

        float lsA = 0.0f, lsB = 0.0f;
#pragma unroll
        for (int nj = 0; nj < 4; nj++) {
            float p0 = __expf(sacc[nj][0] - nmA);
            float p1 = __expf(sacc[nj][1] - nmA);
            float p2 = __expf(sacc[nj][2] - nmB);
            float p3 = __expf(sacc[nj][3] - nmB);
            lsA += p0 + p1; lsB += p2 + p3;
            int col = wn + nj * 8 + 2 * t;
            *(float2*)(&Ps[rA * LQ + col]) = make_float2(p0, p1);
            *(float2*)(&Ps[rB * LQ + col]) = make_float2(p2, p3);
        }
        lsA += __shfl_xor_sync(0xffffffffu, lsA, 1);
        lsA += __shfl_xor_sync(0xffffffffu, lsA, 2);
        lsB += __shfl_xor_sync(0xffffffffu, lsB, 1);
        lsB += __shfl_xor_sync(0xffffffffu, lsB, 2);
        if (t == 0) {
            reds[side * 64 + rA] = lsA;
            reds[side * 64 + rB] = lsB;
        }

#pragma unroll
        for (int nj = 0; nj < 4; nj++) {
            oacc[nj][0] *= alA; oacc[nj][1] *= alA;
            oacc[nj][2] *= alB; oacc[nj][3] *= alB;
        }
        __syncthreads();
        lA = lA * alA + reds[rA] + reds[64 + rA];
        lB = lB * alB + reds[rB] + reds[64 + rB];

#pragma unroll
        for (int ks = 0; ks < 8; ks++) {
            uint32_t ahi[4], alo[4];
            {
                const float* p0 = &Ps[rA * LQ + ks * 8 + t];
                const float* p1 = &Ps[rB * LQ + ks * 8 + t];
                split2(p0[0], ahi[0], alo[0]);
                split2(p1[0], ahi[1], alo[1]);
                split2(p0[4], ahi[2], alo[2]);
                split2(p1[4], ahi[3], alo[3]);
            }
#pragma unroll
            for (int nj = 0; nj < 4; nj++) {
                uint32_t bhi[2], blo[2];
                const float* vp = &Vs[(ks * 8 + t) * LK + wn + nj * 8 + g];
                split2(vp[0],      bhi[0], blo[0]);
                split2(vp[4 * LK], bhi[1], blo[1]);
                mma_tf32(oacc[nj], alo, bhi);
                mma_tf32(oacc[nj], ahi, blo);
                mma_tf32(oacc[nj], ahi, bhi);
            }
        }
    }

    float invA = 1.0f / lA, invB = 1.0f / lB;
#pragma unroll
    for (int nj = 0; nj < 4; nj++) {
        int col = wn + nj * 8 + 2 * t;
        *(float2*)(&g_O[qbase + (size_t)rA * QN + col]) =
            make_float2(oacc[nj][0] * invA, oacc[nj][1] * invA);
        *(float2*)(&g_O[qbase + (size_t)rB * QN + col]) =
            make_float2(oacc[nj][2] * invB, oacc[nj][3] * invB);
    }
}

// ---------------------------------------------------------------------------
extern "C" void kernel_launch(void* const* d_in, const int* in_sizes, int n_in,
                              void* d_out, int out_size)
{
    const float* x    = (const float*)d_in[0];
    const float* freq = (const float*)d_in[1];
    const float* Wq   = (const float*)d_in[2];
    const float* Wk   = (const float*)d_in[3];
    const float* Wv   = (const float*)d_in[4];
    const float* Wo   = (const float*)d_in[5];
    float* out = (float*)d_out;

    void *pQ, *pK, *pV, *pO;
    cudaGetSymbolAddress(&pQ, g_Q);
    cudaGetSymbolAddress(&pK, g_K);
    cudaGetSymbolAddress(&pV, g_V);
    cudaGetSymbolAddress(&pO, g_O);

    cudaFuncSetAttribute(gemm_bf16s_kernel,
                         cudaFuncAttributeMaxDynamicSharedMemorySize,
                         GEMM_SMEM_BYTES);
    cudaFuncSetAttribute(attn_kernel,
                         cudaFuncAttributeMaxDynamicSharedMemorySize, ASM_BYTES);

    // QKV projections (split-bf16 tensor cores)
    gemm_bf16s_kernel<<<dim3(QN / 128, Mrows / 128), 256, GEMM_SMEM_BYTES>>>(
        x, Wq, (float*)pQ, Mrows, QN, Ee);
    gemm_bf16s_kernel<<<dim3(KN / 128, Mrows / 128), 256, GEMM_SMEM_BYTES>>>(
        x, Wk, (float*)pK, Mrows, KN, Ee);
    gemm_bf16s_kernel<<<dim3(KN / 128, Mrows / 128), 256, GEMM_SMEM_BYTES>>>(
        x, Wv, (float*)pV, Mrows, KN, Ee);

    // RoPE
    {
        int totQ = Mrows * Hh * 32;
        rope_kernel<<<(totQ + 255) / 256, 256>>>((float*)pQ, freq, Hh, totQ);
        int totK = Mrows * KVh * 32;
        rope_kernel<<<(totK + 255) / 256, 256>>>((float*)pK, freq, KVh, totK);
    }

    // Attention (3xTF32 HMMA flash, unchanged)
    attn_kernel<<<dim3(Tt / 64, Hh, Bb), 256, ASM_BYTES>>>();

    // Output projection (split-bf16 tensor cores)
    gemm_bf16s_kernel<<<dim3(Ee / 128, Mrows / 128), 256, GEMM_SMEM_BYTES>>>(
        (const float*)pO, Wo, out, Mrows, Ee, QN);
}